// round 6
// baseline (speedup 1.0000x reference)
#include <cuda_runtime.h>
#include <cuda_bf16.h>
#include <mma.h>
#include <cstdint>
#include <cstddef>

using namespace nvcuda;

#define B_   64
#define T_   512
#define H_   256
#define G3_  768
#define M_   (B_*T_)
#define K0_  2048

// recurrence decomposition: 16 batch-groups x 8 unit-groups = 128 CTAs
#define GB_  16
#define GU_  8
#define BC_  4     // batches per CTA
#define UC_  32    // units per CTA
#define RT_  256   // threads = 16 unit-pairs x 16 k-slices
#define WPITCH 260

// GEMM smem geometry
#define TPITCH    72
#define TILE_ELEM (128 * TPITCH)
#define BUF_ELEM  (4 * TILE_ELEM)
#define PSMEM     (2 * BUF_ELEM * 2)

#define RSMEM ((3*UC_*WPITCH + BC_*WPITCH) * (int)sizeof(float))

// ---------------- static device scratch ----------------
__device__ uint16_t g_xh[(size_t)M_*K0_];
__device__ uint16_t g_xl[(size_t)M_*K0_];
__device__ uint16_t g_w0h[G3_*K0_], g_w0l[G3_*K0_];
__device__ uint16_t g_w1h[G3_*H_],  g_w1l[G3_*H_];
__device__ uint16_t g_w2h[G3_*H_],  g_w2l[G3_*H_];
__device__ uint16_t g_seqh[(size_t)M_*H_], g_seql[(size_t)M_*H_];
__device__ float    g_xg_mn[(size_t)M_*G3_];
__device__ float    g_xg[(size_t)T_*G3_*B_];
__device__ float    g_h[2][B_*H_];
__device__ int      g_bar2[3*GB_*T_];

// ---------------- helpers ----------------
__device__ __forceinline__ uint32_t smem_u32(const void* p) {
    uint32_t a;
    asm("{ .reg .u64 t; cvta.to.shared.u64 t, %1; cvt.u32.u64 %0, t; }" : "=r"(a) : "l"(p));
    return a;
}
__device__ __forceinline__ void cp_async16(uint32_t dst, const void* src) {
    asm volatile("cp.async.cg.shared.global [%0], [%1], 16;" :: "r"(dst), "l"(src));
}
__device__ __forceinline__ void cp_commit() {
    asm volatile("cp.async.commit_group;");
}
template<int N>
__device__ __forceinline__ void cp_wait() {
    asm volatile("cp.async.wait_group %0;" :: "n"(N));
}

// ---------------- zero barrier counters ----------------
__global__ void zero_bar_kernel() {
    int i = blockIdx.x * blockDim.x + threadIdx.x;
    if (i < 3 * GB_ * T_) g_bar2[i] = 0;
}

// ---------------- splits ----------------
__global__ void split_x_kernel(const float* __restrict__ src) {
    const size_t n = (size_t)M_ * K0_;
    size_t stride = (size_t)gridDim.x * blockDim.x * 4;
    for (size_t i = ((size_t)blockIdx.x * blockDim.x + threadIdx.x) * 4; i < n; i += stride) {
        float4 v = *(const float4*)(src + i);
        __nv_bfloat16 h0 = __float2bfloat16(v.x), h1 = __float2bfloat16(v.y);
        __nv_bfloat16 h2 = __float2bfloat16(v.z), h3 = __float2bfloat16(v.w);
        __nv_bfloat16* hp = (__nv_bfloat16*)(g_xh + i);
        __nv_bfloat16* lp = (__nv_bfloat16*)(g_xl + i);
        hp[0] = h0; hp[1] = h1; hp[2] = h2; hp[3] = h3;
        lp[0] = __float2bfloat16(v.x - __bfloat162float(h0));
        lp[1] = __float2bfloat16(v.y - __bfloat162float(h1));
        lp[2] = __float2bfloat16(v.z - __bfloat162float(h2));
        lp[3] = __float2bfloat16(v.w - __bfloat162float(h3));
    }
}

__global__ void split_w_kernel(const float* __restrict__ s0,
                               const float* __restrict__ s1,
                               const float* __restrict__ s2) {
    const int a = blockIdx.y;
    const float* src = (a == 0) ? s0 : (a == 1 ? s1 : s2);
    uint16_t* hi = (a == 0) ? g_w0h : (a == 1 ? g_w1h : g_w2h);
    uint16_t* lo = (a == 0) ? g_w0l : (a == 1 ? g_w1l : g_w2l);
    const size_t n = (a == 0) ? (size_t)G3_ * K0_ : (size_t)G3_ * H_;
    size_t stride = (size_t)gridDim.x * blockDim.x * 4;
    for (size_t i = ((size_t)blockIdx.x * blockDim.x + threadIdx.x) * 4; i < n; i += stride) {
        float4 v = *(const float4*)(src + i);
        __nv_bfloat16 h0 = __float2bfloat16(v.x), h1 = __float2bfloat16(v.y);
        __nv_bfloat16 h2 = __float2bfloat16(v.z), h3 = __float2bfloat16(v.w);
        __nv_bfloat16* hp = (__nv_bfloat16*)(hi + i);
        __nv_bfloat16* lp = (__nv_bfloat16*)(lo + i);
        hp[0] = h0; hp[1] = h1; hp[2] = h2; hp[3] = h3;
        lp[0] = __float2bfloat16(v.x - __bfloat162float(h0));
        lp[1] = __float2bfloat16(v.y - __bfloat162float(h1));
        lp[2] = __float2bfloat16(v.z - __bfloat162float(h2));
        lp[3] = __float2bfloat16(v.w - __bfloat162float(h3));
    }
}

// ---------------- WMMA bf16-split projection GEMM ----------------
__global__ __launch_bounds__(256, 1)
void proj_wmma_kernel(int K, int asel, int wsel)
{
    extern __shared__ __nv_bfloat16 smem[];
    const uint32_t sbase = smem_u32(smem);
    const int tid = threadIdx.x;
    const int wid = tid >> 5;
    const int m0 = blockIdx.x * 128;
    const int n0 = blockIdx.y * 128;

    const uint16_t* Ah = asel ? g_seqh : g_xh;
    const uint16_t* Al = asel ? g_seql : g_xl;
    const uint16_t* Bh = (wsel == 0) ? g_w0h : (wsel == 1 ? g_w1h : g_w2h);
    const uint16_t* Bl = (wsel == 0) ? g_w0l : (wsel == 1 ? g_w1l : g_w2l);

    if (blockIdx.x == 0 && blockIdx.y == 0) {
        float4 z = make_float4(0.f, 0.f, 0.f, 0.f);
        float4* hp = reinterpret_cast<float4*>(&g_h[0][0]);
        for (int i = tid; i < 2 * B_ * H_ / 4; i += 256) hp[i] = z;
    }

    const uint16_t* srcs[4] = {Ah + (size_t)m0 * K, Al + (size_t)m0 * K,
                               Bh + (size_t)n0 * K, Bl + (size_t)n0 * K};

    const int nC = K >> 6;

    {
#pragma unroll
        for (int i = 0; i < 16; ++i) {
            int idx  = tid + (i << 8);
            int tile = idx >> 10;
            int rem  = idx & 1023;
            int row  = rem >> 3;
            int c    = rem & 7;
            uint32_t dst = sbase + tile * (TILE_ELEM * 2) + row * (TPITCH * 2) + c * 16;
            cp_async16(dst, srcs[tile] + (size_t)row * K + c * 8);
        }
        cp_commit();
    }

    wmma::fragment<wmma::accumulator, 16, 16, 16, float> acc[2][4];
#pragma unroll
    for (int m = 0; m < 2; ++m)
#pragma unroll
        for (int n = 0; n < 4; ++n) wmma::fill_fragment(acc[m][n], 0.0f);

    const int wm = wid & 3;
    const int wn = wid >> 2;

    for (int c = 0; c < nC; ++c) {
        const int buf = c & 1;
        if (c + 1 < nC) {
            const int k0 = (c + 1) << 6;
            const uint32_t bb = sbase + ((buf ^ 1) ? BUF_ELEM * 2 : 0);
#pragma unroll
            for (int i = 0; i < 16; ++i) {
                int idx  = tid + (i << 8);
                int tile = idx >> 10;
                int rem  = idx & 1023;
                int row  = rem >> 3;
                int cc   = rem & 7;
                uint32_t dst = bb + tile * (TILE_ELEM * 2) + row * (TPITCH * 2) + cc * 16;
                cp_async16(dst, srcs[tile] + (size_t)row * K + k0 + cc * 8);
            }
            cp_commit();
            cp_wait<1>();
        } else {
            cp_wait<0>();
        }
        __syncthreads();

        const __nv_bfloat16* bufp = smem + buf * BUF_ELEM;
        const __nv_bfloat16* sAh = bufp;
        const __nv_bfloat16* sAl = bufp + TILE_ELEM;
        const __nv_bfloat16* sBh = bufp + 2 * TILE_ELEM;
        const __nv_bfloat16* sBl = bufp + 3 * TILE_ELEM;

#pragma unroll
        for (int ks = 0; ks < 4; ++ks) {
            wmma::fragment<wmma::matrix_a, 16, 16, 16, __nv_bfloat16, wmma::row_major> ah[2], al[2];
#pragma unroll
            for (int m = 0; m < 2; ++m) {
                wmma::load_matrix_sync(ah[m], sAh + (wm * 32 + m * 16) * TPITCH + ks * 16, TPITCH);
                wmma::load_matrix_sync(al[m], sAl + (wm * 32 + m * 16) * TPITCH + ks * 16, TPITCH);
            }
#pragma unroll
            for (int n = 0; n < 4; ++n) {
                wmma::fragment<wmma::matrix_b, 16, 16, 16, __nv_bfloat16, wmma::col_major> bh, bl;
                wmma::load_matrix_sync(bh, sBh + (wn * 64 + n * 16) * TPITCH + ks * 16, TPITCH);
#pragma unroll
                for (int m = 0; m < 2; ++m) {
                    wmma::mma_sync(acc[m][n], ah[m], bh, acc[m][n]);
                    wmma::mma_sync(acc[m][n], al[m], bh, acc[m][n]);
                }
                wmma::load_matrix_sync(bl, sBl + (wn * 64 + n * 16) * TPITCH + ks * 16, TPITCH);
#pragma unroll
                for (int m = 0; m < 2; ++m)
                    wmma::mma_sync(acc[m][n], ah[m], bl, acc[m][n]);
            }
        }
        __syncthreads();
    }

#pragma unroll
    for (int m = 0; m < 2; ++m)
#pragma unroll
        for (int n = 0; n < 4; ++n) {
            float* dst = g_xg_mn + (size_t)(m0 + wm * 32 + m * 16) * G3_
                                 + n0 + wn * 64 + n * 16;
            wmma::store_matrix_sync(dst, acc[m][n], G3_, wmma::mem_row_major);
        }
}

// ---------------- transpose [m][n] -> [t][gate][b], add bias ----------------
__global__ __launch_bounds__(256)
void xg_trans_kernel(const float* __restrict__ bias) {
    __shared__ float sm[64][33];
    const int t   = blockIdx.x;
    const int g0  = blockIdx.y * 32;
    const int tid = threadIdx.x;
    const int gg  = tid & 31;
    const int br  = tid >> 5;
    const float bv = bias[g0 + gg];
#pragma unroll
    for (int i = 0; i < 8; ++i) {
        int b = br + i * 8;
        sm[b][gg] = g_xg_mn[((size_t)b * T_ + t) * G3_ + g0 + gg] + bv;
    }
    __syncthreads();
    const int b  = tid & 63;
    const int gi = tid >> 6;
#pragma unroll
    for (int i = 0; i < 8; ++i) {
        int g = gi + i * 4;
        g_xg[((size_t)t * G3_ + g0 + g) * B_ + b] = sm[b][g];
    }
}

// ---------------- persistent GRU recurrence (register-tiled) ----------------
// CTA (bg, ug) owns 4 batches x 32 units. Thread (up, sl): up = unit-pair
// (6 w-rows: 2 units x 3 gates), sl = k-slice (16 k, interleaved by float4).
// 24 accumulators/thread; cross-slice reduction via 16-lane shfl butterfly.
__global__ __launch_bounds__(RT_, 1)
void gru_recur_kernel(const float* __restrict__ w_hh,
                      const float* __restrict__ b_hh,
                      int layer)
{
    extern __shared__ float smf[];
    float* ws = smf;                         // [96][WPITCH]
    float* hs = ws + 3 * UC_ * WPITCH;       // [4][WPITCH]

    const int t   = threadIdx.x;
    const int up  = t >> 4;                  // unit pair 0..15
    const int sl  = t & 15;                  // k slice 0..15
    const int cta = blockIdx.x;
    const int bg  = cta >> 3;
    const int ug  = cta & 7;
    const int b0  = bg * BC_;
    const int u0  = ug * UC_;

    // gate-math lane mapping (lanes sl<8 active): b, unit-in-pair
    const int gb = sl & 3;
    const int gu = (sl >> 2) & 1;
    const int gj = u0 + up * 2 + gu;         // global unit for gate math

    // load this CTA's 96 w_hh rows (3 gates x 32 units)
    for (int q = t; q < 96 * 64; q += RT_) {
        int row = q >> 6;
        int c4  = (q & 63) << 2;
        int g   = row >> 5;
        int uu  = row & 31;
        *(float4*)&ws[row * WPITCH + c4] =
            *(const float4*)&w_hh[((size_t)(g * H_ + u0 + uu)) * H_ + c4];
    }

    const float bhr = b_hh[gj];
    const float bhz = b_hh[H_ + gj];
    const float bhn = b_hh[2 * H_ + gj];
    // w row pointers for this thread's 6 rows
    const float* wrow[3][2];
#pragma unroll
    for (int g = 0; g < 3; ++g)
#pragma unroll
        for (int ui = 0; ui < 2; ++ui)
            wrow[g][ui] = &ws[(g * UC_ + up * 2 + ui) * WPITCH];

    __nv_bfloat16* outh = (__nv_bfloat16*)g_seqh;
    __nv_bfloat16* outl = (__nv_bfloat16*)g_seql;
    int* barp = &g_bar2[(layer * GB_ + bg) * T_];
    __syncthreads();

    for (int step = 0; step < T_; ++step) {
        const float* hcur = g_h[step & 1];
        float*       hnxt = g_h[(step & 1) ^ 1];

        // prefetch xg (precomputed, independent of barrier)
        float xr = 0.f, xz = 0.f, xn = 0.f;
        if (sl < 8) {
            const float* xgp = g_xg + (size_t)step * G3_ * B_;
            xr = __ldg(&xgp[(0 * H_ + gj) * B_ + b0 + gb]);
            xz = __ldg(&xgp[(1 * H_ + gj) * B_ + b0 + gb]);
            xn = __ldg(&xgp[(2 * H_ + gj) * B_ + b0 + gb]);
        }

        // stage h for our 4 batches: 256 float4, one per thread
        {
            int rowb = t >> 6;
            int c4   = (t & 63) << 2;
            float4 v = __ldcg((const float4*)&hcur[(b0 + rowb) * H_ + c4]);
            *(float4*)&hs[rowb * WPITCH + c4] = v;
        }
        __syncthreads();

        // register-tiled dot: 6 rows x 4 batches, k interleaved by slice
        float acc[3][2][4];
#pragma unroll
        for (int g = 0; g < 3; ++g)
#pragma unroll
            for (int ui = 0; ui < 2; ++ui)
#pragma unroll
                for (int b = 0; b < 4; ++b) acc[g][ui][b] = 0.f;

#pragma unroll
        for (int c = 0; c < 4; ++c) {
            const int kb = c * 64 + sl * 4;
            float4 h4[4];
#pragma unroll
            for (int b = 0; b < 4; ++b)
                h4[b] = *(const float4*)&hs[b * WPITCH + kb];
#pragma unroll
            for (int g = 0; g < 3; ++g)
#pragma unroll
                for (int ui = 0; ui < 2; ++ui) {
                    float4 w4 = *(const float4*)&wrow[g][ui][kb];
#pragma unroll
                    for (int b = 0; b < 4; ++b) {
                        acc[g][ui][b] = fmaf(w4.x, h4[b].x, acc[g][ui][b]);
                        acc[g][ui][b] = fmaf(w4.y, h4[b].y, acc[g][ui][b]);
                        acc[g][ui][b] = fmaf(w4.z, h4[b].z, acc[g][ui][b]);
                        acc[g][ui][b] = fmaf(w4.w, h4[b].w, acc[g][ui][b]);
                    }
                }
        }

        // 16-lane butterfly reduction across k-slices (stays in up-group)
#pragma unroll
        for (int off = 8; off >= 1; off >>= 1)
#pragma unroll
            for (int g = 0; g < 3; ++g)
#pragma unroll
                for (int ui = 0; ui < 2; ++ui)
#pragma unroll
                    for (int b = 0; b < 4; ++b)
                        acc[g][ui][b] += __shfl_xor_sync(0xffffffffu, acc[g][ui][b], off);

        float hnew = 0.f;
        if (sl < 8) {
            float ar = acc[0][gu][gb];
            float az = acc[1][gu][gb];
            float an = acc[2][gu][gb];
            float r = 1.0f / (1.0f + __expf(-(xr + ar + bhr)));
            float z = 1.0f / (1.0f + __expf(-(xz + az + bhz)));
            float n = tanhf(xn + r * (an + bhn));
            float hold = hs[gb * WPITCH + gj];
            hnew = (1.0f - z) * n + z * hold;
            __stcg(&hnxt[(b0 + gb) * H_ + gj], hnew);
        }

        if (step + 1 < T_) {
            __threadfence();
            __syncthreads();
            int arrived = GU_;
            if (t == 0) arrived = atomicAdd(&barp[step], 1) + 1;

            // overlap: seq outputs while peers arrive
            if (sl < 8) {
                __nv_bfloat16 hh = __float2bfloat16(hnew);
                __nv_bfloat16 hl = __float2bfloat16(hnew - __bfloat162float(hh));
                size_t o = ((size_t)(b0 + gb) * T_ + step) * H_ + gj;
                outh[o] = hh;
                outl[o] = hl;
            }

            if (t == 0 && arrived < GU_) {
                volatile int* rp = &barp[step];
                while (*rp < GU_) { }
            }
            __syncthreads();
        } else {
            if (sl < 8) {
                __nv_bfloat16 hh = __float2bfloat16(hnew);
                __nv_bfloat16 hl = __float2bfloat16(hnew - __bfloat162float(hh));
                size_t o = ((size_t)(b0 + gb) * T_ + step) * H_ + gj;
                outh[o] = hh;
                outl[o] = hl;
            }
        }
    }
}

// ---------------- MLP head ----------------
__global__ void head_kernel(const float* __restrict__ fc1_w,
                            const float* __restrict__ fc1_b,
                            const float* __restrict__ fco_w,
                            const float* __restrict__ fco_b,
                            float* __restrict__ outp)
{
    const int b = blockIdx.x;
    const int f = threadIdx.x;
    const float* last = &g_h[0][b * H_];
    float acc = fc1_b[f];
#pragma unroll 4
    for (int k = 0; k < H_; k += 4) {
        float4 l4 = *(const float4*)&last[k];
        float4 w4 = *(const float4*)&fc1_w[(size_t)f * H_ + k];
        acc = fmaf(l4.x, w4.x, acc); acc = fmaf(l4.y, w4.y, acc);
        acc = fmaf(l4.z, w4.z, acc); acc = fmaf(l4.w, w4.w, acc);
    }
    float zz = fmaxf(acc, 0.0f) * fco_w[f];
#pragma unroll
    for (int o = 16; o > 0; o >>= 1)
        zz += __shfl_down_sync(0xffffffffu, zz, o);
    __shared__ float red4[4];
    if ((f & 31) == 0) red4[f >> 5] = zz;
    __syncthreads();
    if (f == 0) outp[b] = red4[0] + red4[1] + red4[2] + red4[3] + fco_b[0];
}

// ---------------- launch ----------------
extern "C" void kernel_launch(void* const* d_in, const int* in_sizes, int n_in,
                              void* d_out, int out_size) {
    (void)in_sizes; (void)n_in; (void)out_size;
    const float* x      = (const float*)d_in[0];
    const float* wih[3] = {(const float*)d_in[1], (const float*)d_in[5], (const float*)d_in[9]};
    const float* whh[3] = {(const float*)d_in[2], (const float*)d_in[6], (const float*)d_in[10]};
    const float* bih[3] = {(const float*)d_in[3], (const float*)d_in[7], (const float*)d_in[11]};
    const float* bhh[3] = {(const float*)d_in[4], (const float*)d_in[8], (const float*)d_in[12]};
    const float* fc1_w  = (const float*)d_in[13];
    const float* fc1_b  = (const float*)d_in[14];
    const float* fco_w  = (const float*)d_in[15];
    const float* fco_b  = (const float*)d_in[16];
    float* outp = (float*)d_out;

    cudaFuncSetAttribute(proj_wmma_kernel,
                         cudaFuncAttributeMaxDynamicSharedMemorySize, PSMEM);
    cudaFuncSetAttribute(gru_recur_kernel,
                         cudaFuncAttributeMaxDynamicSharedMemorySize, RSMEM);

    zero_bar_kernel<<<96, 256>>>();                                 // 1
    split_x_kernel<<<2048, 256>>>(x);                               // 2
    split_w_kernel<<<dim3(256, 3), 256>>>(wih[0], wih[1], wih[2]);  // 3

    dim3 pgrid(M_ / 128, G3_ / 128);
    dim3 tgrid(T_, G3_ / 32);
    const int Ks[3]   = {K0_, H_, H_};
    const int asel[3] = {0, 1, 1};

    for (int l = 0; l < 3; ++l) {
        proj_wmma_kernel<<<pgrid, 256, PSMEM>>>(Ks[l], asel[l], l);   // 4
        xg_trans_kernel<<<tgrid, 256>>>(bih[l]);                      // 5
        gru_recur_kernel<<<GB_ * GU_, RT_, RSMEM>>>(whh[l], bhh[l], l); // 6 <- ncu target
    }
    head_kernel<<<B_, 128>>>(fc1_w, fc1_b, fco_w, fco_b, outp);
}

// round 7
// speedup vs baseline: 1.1004x; 1.1004x over previous
#include <cuda_runtime.h>
#include <cuda_bf16.h>
#include <mma.h>
#include <cstdint>
#include <cstddef>

using namespace nvcuda;

#define B_   64
#define T_   512
#define H_   256
#define G3_  768
#define M_   (B_*T_)
#define K0_  2048

// recurrence decomposition: 16 batch-groups x 8 unit-groups = 128 CTAs
#define GB_  16
#define GU_  8
#define BC_  4     // batches per CTA
#define UC_  32    // units per CTA
#define RT_  256   // threads = 32 units x 8 k-slices
#define WPITCH 260

// GEMM smem geometry
#define TPITCH    72
#define TILE_ELEM (128 * TPITCH)
#define BUF_ELEM  (4 * TILE_ELEM)
#define PSMEM     (2 * BUF_ELEM * 2)

#define RSMEM ((3*UC_*WPITCH + BC_*WPITCH) * (int)sizeof(float))

// ---------------- static device scratch ----------------
__device__ uint16_t g_xh[(size_t)M_*K0_];
__device__ uint16_t g_xl[(size_t)M_*K0_];
__device__ uint16_t g_w0h[G3_*K0_], g_w0l[G3_*K0_];
__device__ uint16_t g_w1h[G3_*H_],  g_w1l[G3_*H_];
__device__ uint16_t g_w2h[G3_*H_],  g_w2l[G3_*H_];
__device__ uint16_t g_seqh[(size_t)M_*H_], g_seql[(size_t)M_*H_];
__device__ float    g_xg_mn[(size_t)M_*G3_];
__device__ float    g_xg[(size_t)T_*G3_*B_];
__device__ float    g_h[2][B_*H_];
__device__ int      g_bar2[3*GB_*T_];

// ---------------- helpers ----------------
__device__ __forceinline__ uint32_t smem_u32(const void* p) {
    uint32_t a;
    asm("{ .reg .u64 t; cvta.to.shared.u64 t, %1; cvt.u32.u64 %0, t; }" : "=r"(a) : "l"(p));
    return a;
}
__device__ __forceinline__ void cp_async16(uint32_t dst, const void* src) {
    asm volatile("cp.async.cg.shared.global [%0], [%1], 16;" :: "r"(dst), "l"(src));
}
__device__ __forceinline__ void cp_commit() {
    asm volatile("cp.async.commit_group;");
}
template<int N>
__device__ __forceinline__ void cp_wait() {
    asm volatile("cp.async.wait_group %0;" :: "n"(N));
}

// ---------------- zero barrier counters ----------------
__global__ void zero_bar_kernel() {
    int i = blockIdx.x * blockDim.x + threadIdx.x;
    if (i < 3 * GB_ * T_) g_bar2[i] = 0;
}

// ---------------- splits ----------------
__global__ void split_x_kernel(const float* __restrict__ src) {
    const size_t n = (size_t)M_ * K0_;
    size_t stride = (size_t)gridDim.x * blockDim.x * 4;
    for (size_t i = ((size_t)blockIdx.x * blockDim.x + threadIdx.x) * 4; i < n; i += stride) {
        float4 v = *(const float4*)(src + i);
        __nv_bfloat16 h0 = __float2bfloat16(v.x), h1 = __float2bfloat16(v.y);
        __nv_bfloat16 h2 = __float2bfloat16(v.z), h3 = __float2bfloat16(v.w);
        __nv_bfloat16* hp = (__nv_bfloat16*)(g_xh + i);
        __nv_bfloat16* lp = (__nv_bfloat16*)(g_xl + i);
        hp[0] = h0; hp[1] = h1; hp[2] = h2; hp[3] = h3;
        lp[0] = __float2bfloat16(v.x - __bfloat162float(h0));
        lp[1] = __float2bfloat16(v.y - __bfloat162float(h1));
        lp[2] = __float2bfloat16(v.z - __bfloat162float(h2));
        lp[3] = __float2bfloat16(v.w - __bfloat162float(h3));
    }
}

__global__ void split_w_kernel(const float* __restrict__ s0,
                               const float* __restrict__ s1,
                               const float* __restrict__ s2) {
    const int a = blockIdx.y;
    const float* src = (a == 0) ? s0 : (a == 1 ? s1 : s2);
    uint16_t* hi = (a == 0) ? g_w0h : (a == 1 ? g_w1h : g_w2h);
    uint16_t* lo = (a == 0) ? g_w0l : (a == 1 ? g_w1l : g_w2l);
    const size_t n = (a == 0) ? (size_t)G3_ * K0_ : (size_t)G3_ * H_;
    size_t stride = (size_t)gridDim.x * blockDim.x * 4;
    for (size_t i = ((size_t)blockIdx.x * blockDim.x + threadIdx.x) * 4; i < n; i += stride) {
        float4 v = *(const float4*)(src + i);
        __nv_bfloat16 h0 = __float2bfloat16(v.x), h1 = __float2bfloat16(v.y);
        __nv_bfloat16 h2 = __float2bfloat16(v.z), h3 = __float2bfloat16(v.w);
        __nv_bfloat16* hp = (__nv_bfloat16*)(hi + i);
        __nv_bfloat16* lp = (__nv_bfloat16*)(lo + i);
        hp[0] = h0; hp[1] = h1; hp[2] = h2; hp[3] = h3;
        lp[0] = __float2bfloat16(v.x - __bfloat162float(h0));
        lp[1] = __float2bfloat16(v.y - __bfloat162float(h1));
        lp[2] = __float2bfloat16(v.z - __bfloat162float(h2));
        lp[3] = __float2bfloat16(v.w - __bfloat162float(h3));
    }
}

// ---------------- WMMA bf16-split projection GEMM ----------------
__global__ __launch_bounds__(256, 1)
void proj_wmma_kernel(int K, int asel, int wsel)
{
    extern __shared__ __nv_bfloat16 smem[];
    const uint32_t sbase = smem_u32(smem);
    const int tid = threadIdx.x;
    const int wid = tid >> 5;
    const int m0 = blockIdx.x * 128;
    const int n0 = blockIdx.y * 128;

    const uint16_t* Ah = asel ? g_seqh : g_xh;
    const uint16_t* Al = asel ? g_seql : g_xl;
    const uint16_t* Bh = (wsel == 0) ? g_w0h : (wsel == 1 ? g_w1h : g_w2h);
    const uint16_t* Bl = (wsel == 0) ? g_w0l : (wsel == 1 ? g_w1l : g_w2l);

    if (blockIdx.x == 0 && blockIdx.y == 0) {
        float4 z = make_float4(0.f, 0.f, 0.f, 0.f);
        float4* hp = reinterpret_cast<float4*>(&g_h[0][0]);
        for (int i = tid; i < 2 * B_ * H_ / 4; i += 256) hp[i] = z;
    }

    const uint16_t* srcs[4] = {Ah + (size_t)m0 * K, Al + (size_t)m0 * K,
                               Bh + (size_t)n0 * K, Bl + (size_t)n0 * K};

    const int nC = K >> 6;

    {
#pragma unroll
        for (int i = 0; i < 16; ++i) {
            int idx  = tid + (i << 8);
            int tile = idx >> 10;
            int rem  = idx & 1023;
            int row  = rem >> 3;
            int c    = rem & 7;
            uint32_t dst = sbase + tile * (TILE_ELEM * 2) + row * (TPITCH * 2) + c * 16;
            cp_async16(dst, srcs[tile] + (size_t)row * K + c * 8);
        }
        cp_commit();
    }

    wmma::fragment<wmma::accumulator, 16, 16, 16, float> acc[2][4];
#pragma unroll
    for (int m = 0; m < 2; ++m)
#pragma unroll
        for (int n = 0; n < 4; ++n) wmma::fill_fragment(acc[m][n], 0.0f);

    const int wm = wid & 3;
    const int wn = wid >> 2;

    for (int c = 0; c < nC; ++c) {
        const int buf = c & 1;
        if (c + 1 < nC) {
            const int k0 = (c + 1) << 6;
            const uint32_t bb = sbase + ((buf ^ 1) ? BUF_ELEM * 2 : 0);
#pragma unroll
            for (int i = 0; i < 16; ++i) {
                int idx  = tid + (i << 8);
                int tile = idx >> 10;
                int rem  = idx & 1023;
                int row  = rem >> 3;
                int cc   = rem & 7;
                uint32_t dst = bb + tile * (TILE_ELEM * 2) + row * (TPITCH * 2) + cc * 16;
                cp_async16(dst, srcs[tile] + (size_t)row * K + k0 + cc * 8);
            }
            cp_commit();
            cp_wait<1>();
        } else {
            cp_wait<0>();
        }
        __syncthreads();

        const __nv_bfloat16* bufp = smem + buf * BUF_ELEM;
        const __nv_bfloat16* sAh = bufp;
        const __nv_bfloat16* sAl = bufp + TILE_ELEM;
        const __nv_bfloat16* sBh = bufp + 2 * TILE_ELEM;
        const __nv_bfloat16* sBl = bufp + 3 * TILE_ELEM;

#pragma unroll
        for (int ks = 0; ks < 4; ++ks) {
            wmma::fragment<wmma::matrix_a, 16, 16, 16, __nv_bfloat16, wmma::row_major> ah[2], al[2];
#pragma unroll
            for (int m = 0; m < 2; ++m) {
                wmma::load_matrix_sync(ah[m], sAh + (wm * 32 + m * 16) * TPITCH + ks * 16, TPITCH);
                wmma::load_matrix_sync(al[m], sAl + (wm * 32 + m * 16) * TPITCH + ks * 16, TPITCH);
            }
#pragma unroll
            for (int n = 0; n < 4; ++n) {
                wmma::fragment<wmma::matrix_b, 16, 16, 16, __nv_bfloat16, wmma::col_major> bh, bl;
                wmma::load_matrix_sync(bh, sBh + (wn * 64 + n * 16) * TPITCH + ks * 16, TPITCH);
#pragma unroll
                for (int m = 0; m < 2; ++m) {
                    wmma::mma_sync(acc[m][n], ah[m], bh, acc[m][n]);
                    wmma::mma_sync(acc[m][n], al[m], bh, acc[m][n]);
                }
                wmma::load_matrix_sync(bl, sBl + (wn * 64 + n * 16) * TPITCH + ks * 16, TPITCH);
#pragma unroll
                for (int m = 0; m < 2; ++m)
                    wmma::mma_sync(acc[m][n], ah[m], bl, acc[m][n]);
            }
        }
        __syncthreads();
    }

#pragma unroll
    for (int m = 0; m < 2; ++m)
#pragma unroll
        for (int n = 0; n < 4; ++n) {
            float* dst = g_xg_mn + (size_t)(m0 + wm * 32 + m * 16) * G3_
                                 + n0 + wn * 64 + n * 16;
            wmma::store_matrix_sync(dst, acc[m][n], G3_, wmma::mem_row_major);
        }
}

// ---------------- transpose [m][n] -> [t][gate][b], add bias ----------------
__global__ __launch_bounds__(256)
void xg_trans_kernel(const float* __restrict__ bias) {
    __shared__ float sm[64][33];
    const int t   = blockIdx.x;
    const int g0  = blockIdx.y * 32;
    const int tid = threadIdx.x;
    const int gg  = tid & 31;
    const int br  = tid >> 5;
    const float bv = bias[g0 + gg];
#pragma unroll
    for (int i = 0; i < 8; ++i) {
        int b = br + i * 8;
        sm[b][gg] = g_xg_mn[((size_t)b * T_ + t) * G3_ + g0 + gg] + bv;
    }
    __syncthreads();
    const int b  = tid & 63;
    const int gi = tid >> 6;
#pragma unroll
    for (int i = 0; i < 8; ++i) {
        int g = gi + i * 4;
        g_xg[((size_t)t * G3_ + g0 + g) * B_ + b] = sm[b][g];
    }
}

// ---------------- persistent GRU recurrence ----------------
// CTA (bg, ug): 4 batches x 32 units. Thread t = u*8 + sl: unit u, k-slice sl
// (32 k, float4-interleaved). 12 accumulators (3 gates x 4 batches); per 4-k
// chunk: 4 h-float4 (broadcast) + 3 w-float4 for 48 FMA. Cross-slice reduce:
// 3-round shfl_xor in 8-lane groups (36 shfl). Lanes sl<4 finish batch sl.
__global__ __launch_bounds__(RT_, 1)
void gru_recur_kernel(const float* __restrict__ w_hh,
                      const float* __restrict__ b_hh,
                      int layer)
{
    extern __shared__ float smf[];
    float* ws = smf;                         // [96][WPITCH]
    float* hs = ws + 3 * UC_ * WPITCH;       // [4][WPITCH]

    const int t   = threadIdx.x;
    const int u   = t >> 3;                  // unit 0..31
    const int sl  = t & 7;                   // k slice 0..7
    const int cta = blockIdx.x;
    const int bg  = cta >> 3;
    const int ug  = cta & 7;
    const int b0  = bg * BC_;
    const int u0  = ug * UC_;
    const int gj  = u0 + u;                  // global unit

    // load this CTA's 96 w_hh rows (3 gates x 32 units)
    for (int q = t; q < 96 * 64; q += RT_) {
        int row = q >> 6;
        int c4  = (q & 63) << 2;
        int g   = row >> 5;
        int uu  = row & 31;
        *(float4*)&ws[row * WPITCH + c4] =
            *(const float4*)&w_hh[((size_t)(g * H_ + u0 + uu)) * H_ + c4];
    }

    const float bhr = b_hh[gj];
    const float bhz = b_hh[H_ + gj];
    const float bhn = b_hh[2 * H_ + gj];
    const float* wr = &ws[(0 * UC_ + u) * WPITCH];
    const float* wz = &ws[(1 * UC_ + u) * WPITCH];
    const float* wn = &ws[(2 * UC_ + u) * WPITCH];

    __nv_bfloat16* outh = (__nv_bfloat16*)g_seqh;
    __nv_bfloat16* outl = (__nv_bfloat16*)g_seql;
    int* barp = &g_bar2[(layer * GB_ + bg) * T_];
    __syncthreads();

    for (int step = 0; step < T_; ++step) {
        const float* hcur = g_h[step & 1];
        float*       hnxt = g_h[(step & 1) ^ 1];

        // prefetch xg (precomputed, independent of barrier): lanes sl<4, batch sl
        float xr = 0.f, xz = 0.f, xn = 0.f;
        if (sl < 4) {
            const float* xgp = g_xg + (size_t)step * G3_ * B_;
            xr = __ldg(&xgp[(0 * H_ + gj) * B_ + b0 + sl]);
            xz = __ldg(&xgp[(1 * H_ + gj) * B_ + b0 + sl]);
            xn = __ldg(&xgp[(2 * H_ + gj) * B_ + b0 + sl]);
        }

        // stage h for our 4 batches: 256 float4, one per thread
        {
            int rowb = t >> 6;
            int c4   = (t & 63) << 2;
            float4 v = __ldcg((const float4*)&hcur[(b0 + rowb) * H_ + c4]);
            *(float4*)&hs[rowb * WPITCH + c4] = v;
        }
        __syncthreads();

        // 3 gates x 4 batches over this thread's 32-k slice (interleaved)
        float acc[3][4];
#pragma unroll
        for (int g = 0; g < 3; ++g)
#pragma unroll
            for (int b = 0; b < 4; ++b) acc[g][b] = 0.f;

#pragma unroll
        for (int c = 0; c < 8; ++c) {
            const int kb = c * 32 + sl * 4;
            float4 h4[4];
#pragma unroll
            for (int b = 0; b < 4; ++b)
                h4[b] = *(const float4*)&hs[b * WPITCH + kb];
            {
                float4 w4 = *(const float4*)&wr[kb];
#pragma unroll
                for (int b = 0; b < 4; ++b) {
                    acc[0][b] = fmaf(w4.x, h4[b].x, acc[0][b]);
                    acc[0][b] = fmaf(w4.y, h4[b].y, acc[0][b]);
                    acc[0][b] = fmaf(w4.z, h4[b].z, acc[0][b]);
                    acc[0][b] = fmaf(w4.w, h4[b].w, acc[0][b]);
                }
            }
            {
                float4 w4 = *(const float4*)&wz[kb];
#pragma unroll
                for (int b = 0; b < 4; ++b) {
                    acc[1][b] = fmaf(w4.x, h4[b].x, acc[1][b]);
                    acc[1][b] = fmaf(w4.y, h4[b].y, acc[1][b]);
                    acc[1][b] = fmaf(w4.z, h4[b].z, acc[1][b]);
                    acc[1][b] = fmaf(w4.w, h4[b].w, acc[1][b]);
                }
            }
            {
                float4 w4 = *(const float4*)&wn[kb];
#pragma unroll
                for (int b = 0; b < 4; ++b) {
                    acc[2][b] = fmaf(w4.x, h4[b].x, acc[2][b]);
                    acc[2][b] = fmaf(w4.y, h4[b].y, acc[2][b]);
                    acc[2][b] = fmaf(w4.z, h4[b].z, acc[2][b]);
                    acc[2][b] = fmaf(w4.w, h4[b].w, acc[2][b]);
                }
            }
        }

        // reduce across 8 k-slices (3-round butterfly inside 8-lane groups)
#pragma unroll
        for (int off = 4; off >= 1; off >>= 1)
#pragma unroll
            for (int g = 0; g < 3; ++g)
#pragma unroll
                for (int b = 0; b < 4; ++b)
                    acc[g][b] += __shfl_xor_sync(0xffffffffu, acc[g][b], off);

        float hnew = 0.f;
        if (sl < 4) {
            float r = 1.0f / (1.0f + __expf(-(xr + acc[0][sl] + bhr)));
            float z = 1.0f / (1.0f + __expf(-(xz + acc[1][sl] + bhz)));
            float n = tanhf(xn + r * (acc[2][sl] + bhn));
            float hold = hs[sl * WPITCH + gj];
            hnew = (1.0f - z) * n + z * hold;
            __stcg(&hnxt[(b0 + sl) * H_ + gj], hnew);
        }

        if (step + 1 < T_) {
            __threadfence();
            __syncthreads();
            int arrived = GU_;
            if (t == 0) arrived = atomicAdd(&barp[step], 1) + 1;

            // overlap: seq outputs while peers arrive
            if (sl < 4) {
                __nv_bfloat16 hh = __float2bfloat16(hnew);
                __nv_bfloat16 hl = __float2bfloat16(hnew - __bfloat162float(hh));
                size_t o = ((size_t)(b0 + sl) * T_ + step) * H_ + gj;
                outh[o] = hh;
                outl[o] = hl;
            }

            if (t == 0 && arrived < GU_) {
                volatile int* rp = &barp[step];
                while (*rp < GU_) { }
            }
            __syncthreads();
        } else {
            if (sl < 4) {
                __nv_bfloat16 hh = __float2bfloat16(hnew);
                __nv_bfloat16 hl = __float2bfloat16(hnew - __bfloat162float(hh));
                size_t o = ((size_t)(b0 + sl) * T_ + step) * H_ + gj;
                outh[o] = hh;
                outl[o] = hl;
            }
        }
    }
}

// ---------------- MLP head ----------------
__global__ void head_kernel(const float* __restrict__ fc1_w,
                            const float* __restrict__ fc1_b,
                            const float* __restrict__ fco_w,
                            const float* __restrict__ fco_b,
                            float* __restrict__ outp)
{
    const int b = blockIdx.x;
    const int f = threadIdx.x;
    const float* last = &g_h[0][b * H_];
    float acc = fc1_b[f];
#pragma unroll 4
    for (int k = 0; k < H_; k += 4) {
        float4 l4 = *(const float4*)&last[k];
        float4 w4 = *(const float4*)&fc1_w[(size_t)f * H_ + k];
        acc = fmaf(l4.x, w4.x, acc); acc = fmaf(l4.y, w4.y, acc);
        acc = fmaf(l4.z, w4.z, acc); acc = fmaf(l4.w, w4.w, acc);
    }
    float zz = fmaxf(acc, 0.0f) * fco_w[f];
#pragma unroll
    for (int o = 16; o > 0; o >>= 1)
        zz += __shfl_down_sync(0xffffffffu, zz, o);
    __shared__ float red4[4];
    if ((f & 31) == 0) red4[f >> 5] = zz;
    __syncthreads();
    if (f == 0) outp[b] = red4[0] + red4[1] + red4[2] + red4[3] + fco_b[0];
}

// ---------------- launch ----------------
extern "C" void kernel_launch(void* const* d_in, const int* in_sizes, int n_in,
                              void* d_out, int out_size) {
    (void)in_sizes; (void)n_in; (void)out_size;
    const float* x      = (const float*)d_in[0];
    const float* wih[3] = {(const float*)d_in[1], (const float*)d_in[5], (const float*)d_in[9]};
    const float* whh[3] = {(const float*)d_in[2], (const float*)d_in[6], (const float*)d_in[10]};
    const float* bih[3] = {(const float*)d_in[3], (const float*)d_in[7], (const float*)d_in[11]};
    const float* bhh[3] = {(const float*)d_in[4], (const float*)d_in[8], (const float*)d_in[12]};
    const float* fc1_w  = (const float*)d_in[13];
    const float* fc1_b  = (const float*)d_in[14];
    const float* fco_w  = (const float*)d_in[15];
    const float* fco_b  = (const float*)d_in[16];
    float* outp = (float*)d_out;

    cudaFuncSetAttribute(proj_wmma_kernel,
                         cudaFuncAttributeMaxDynamicSharedMemorySize, PSMEM);
    cudaFuncSetAttribute(gru_recur_kernel,
                         cudaFuncAttributeMaxDynamicSharedMemorySize, RSMEM);

    zero_bar_kernel<<<96, 256>>>();                                 // 1
    split_x_kernel<<<2048, 256>>>(x);                               // 2
    split_w_kernel<<<dim3(256, 3), 256>>>(wih[0], wih[1], wih[2]);  // 3

    dim3 pgrid(M_ / 128, G3_ / 128);
    dim3 tgrid(T_, G3_ / 32);
    const int Ks[3]   = {K0_, H_, H_};
    const int asel[3] = {0, 1, 1};

    for (int l = 0; l < 3; ++l) {
        proj_wmma_kernel<<<pgrid, 256, PSMEM>>>(Ks[l], asel[l], l);   // 4
        xg_trans_kernel<<<tgrid, 256>>>(bih[l]);                      // 5
        gru_recur_kernel<<<GB_ * GU_, RT_, RSMEM>>>(whh[l], bhh[l], l); // 6 <- ncu target
    }
    head_kernel<<<B_, 128>>>(fc1_w, fc1_b, fco_w, fco_b, outp);
}

// round 8
// speedup vs baseline: 1.1294x; 1.0263x over previous
#include <cuda_runtime.h>
#include <cuda_bf16.h>
#include <mma.h>
#include <cstdint>
#include <cstddef>

using namespace nvcuda;

#define B_   64
#define T_   512
#define H_   256
#define G3_  768
#define M_   (B_*T_)
#define K0_  2048

// recurrence: 16 batch-groups, each an 8-CTA cluster (one CTA per 32 units)
#define GB_  16
#define GU_  8
#define BC_  4     // batches per group
#define UC_  32    // units per CTA
#define RT_  256   // threads = 32 units x 8 k-slices
#define WPITCH 260

// GEMM smem geometry
#define TPITCH    72
#define TILE_ELEM (128 * TPITCH)
#define BUF_ELEM  (4 * TILE_ELEM)
#define PSMEM     (2 * BUF_ELEM * 2)

// recurrence smem: 16 floats mbar/pad + ws[96][WPITCH] + hs[2][4][WPITCH]
#define RSMEM ((16 + 3*UC_*WPITCH + 2*BC_*WPITCH) * (int)sizeof(float))

// ---------------- static device scratch ----------------
__device__ uint16_t g_xh[(size_t)M_*K0_];
__device__ uint16_t g_xl[(size_t)M_*K0_];
__device__ uint16_t g_w0h[G3_*K0_], g_w0l[G3_*K0_];
__device__ uint16_t g_w1h[G3_*H_],  g_w1l[G3_*H_];
__device__ uint16_t g_w2h[G3_*H_],  g_w2l[G3_*H_];
__device__ uint16_t g_seqh[(size_t)M_*H_], g_seql[(size_t)M_*H_];
__device__ float    g_xg_mn[(size_t)M_*G3_];
__device__ float    g_xg[(size_t)T_*G3_*B_];
__device__ float    g_h[2][B_*H_];

// ---------------- helpers ----------------
__device__ __forceinline__ uint32_t smem_u32(const void* p) {
    uint32_t a;
    asm("{ .reg .u64 t; cvta.to.shared.u64 t, %1; cvt.u32.u64 %0, t; }" : "=r"(a) : "l"(p));
    return a;
}
__device__ __forceinline__ void cp_async16(uint32_t dst, const void* src) {
    asm volatile("cp.async.cg.shared.global [%0], [%1], 16;" :: "r"(dst), "l"(src));
}
__device__ __forceinline__ void cp_commit() {
    asm volatile("cp.async.commit_group;");
}
template<int N>
__device__ __forceinline__ void cp_wait() {
    asm volatile("cp.async.wait_group %0;" :: "n"(N));
}
__device__ __forceinline__ uint32_t cluster_rank() {
    uint32_t r;
    asm("mov.u32 %0, %%cluster_ctarank;" : "=r"(r));
    return r;
}
#define MBARRIER_INIT(a, c) \
    asm volatile("mbarrier.init.shared.b64 [%0], %1;" :: "r"(a), "r"(c) : "memory")
#define CLUSTER_SYNC() do { \
    asm volatile("barrier.cluster.arrive.aligned;" ::: "memory"); \
    asm volatile("barrier.cluster.wait.aligned;" ::: "memory"); \
} while (0)
#define MBARRIER_WAIT_CLUSTER(mbar, ph) do { \
    uint32_t _done; \
    asm volatile("{\n\t.reg .pred p;\n\t" \
        "mbarrier.try_wait.parity.acquire.cluster.shared::cta.b64 p, [%1], %2;\n\t" \
        "selp.b32 %0, 1, 0, p;\n\t}" \
        : "=r"(_done) : "r"(mbar), "r"(ph) : "memory"); \
    if (!_done) { \
        asm volatile("{\n\t.reg .pred P;\n\t" \
            "WLC_%=:\n\t" \
            "mbarrier.try_wait.parity.acquire.cluster.shared::cta.b64 P, [%0], %1, 0x989680;\n\t" \
            "@P bra.uni WDC_%=;\n\t" \
            "bra.uni WLC_%=;\n\t" \
            "WDC_%=:\n\t}" \
            :: "r"(mbar), "r"(ph) : "memory"); \
    } \
} while (0)

// ---------------- init ----------------
__global__ void init_kernel() {
    int i = blockIdx.x * blockDim.x + threadIdx.x;
    if (i < 2 * B_ * H_) ((float*)g_h)[i] = 0.0f;
}

// ---------------- splits ----------------
__global__ void split_x_kernel(const float* __restrict__ src) {
    const size_t n = (size_t)M_ * K0_;
    size_t stride = (size_t)gridDim.x * blockDim.x * 4;
    for (size_t i = ((size_t)blockIdx.x * blockDim.x + threadIdx.x) * 4; i < n; i += stride) {
        float4 v = *(const float4*)(src + i);
        __nv_bfloat16 h0 = __float2bfloat16(v.x), h1 = __float2bfloat16(v.y);
        __nv_bfloat16 h2 = __float2bfloat16(v.z), h3 = __float2bfloat16(v.w);
        __nv_bfloat16* hp = (__nv_bfloat16*)(g_xh + i);
        __nv_bfloat16* lp = (__nv_bfloat16*)(g_xl + i);
        hp[0] = h0; hp[1] = h1; hp[2] = h2; hp[3] = h3;
        lp[0] = __float2bfloat16(v.x - __bfloat162float(h0));
        lp[1] = __float2bfloat16(v.y - __bfloat162float(h1));
        lp[2] = __float2bfloat16(v.z - __bfloat162float(h2));
        lp[3] = __float2bfloat16(v.w - __bfloat162float(h3));
    }
}

__global__ void split_w_kernel(const float* __restrict__ s0,
                               const float* __restrict__ s1,
                               const float* __restrict__ s2) {
    const int a = blockIdx.y;
    const float* src = (a == 0) ? s0 : (a == 1 ? s1 : s2);
    uint16_t* hi = (a == 0) ? g_w0h : (a == 1 ? g_w1h : g_w2h);
    uint16_t* lo = (a == 0) ? g_w0l : (a == 1 ? g_w1l : g_w2l);
    const size_t n = (a == 0) ? (size_t)G3_ * K0_ : (size_t)G3_ * H_;
    size_t stride = (size_t)gridDim.x * blockDim.x * 4;
    for (size_t i = ((size_t)blockIdx.x * blockDim.x + threadIdx.x) * 4; i < n; i += stride) {
        float4 v = *(const float4*)(src + i);
        __nv_bfloat16 h0 = __float2bfloat16(v.x), h1 = __float2bfloat16(v.y);
        __nv_bfloat16 h2 = __float2bfloat16(v.z), h3 = __float2bfloat16(v.w);
        __nv_bfloat16* hp = (__nv_bfloat16*)(hi + i);
        __nv_bfloat16* lp = (__nv_bfloat16*)(lo + i);
        hp[0] = h0; hp[1] = h1; hp[2] = h2; hp[3] = h3;
        lp[0] = __float2bfloat16(v.x - __bfloat162float(h0));
        lp[1] = __float2bfloat16(v.y - __bfloat162float(h1));
        lp[2] = __float2bfloat16(v.z - __bfloat162float(h2));
        lp[3] = __float2bfloat16(v.w - __bfloat162float(h3));
    }
}

// ---------------- WMMA bf16-split projection GEMM ----------------
__global__ __launch_bounds__(256, 1)
void proj_wmma_kernel(int K, int asel, int wsel)
{
    extern __shared__ __nv_bfloat16 smem[];
    const uint32_t sbase = smem_u32(smem);
    const int tid = threadIdx.x;
    const int wid = tid >> 5;
    const int m0 = blockIdx.x * 128;
    const int n0 = blockIdx.y * 128;

    const uint16_t* Ah = asel ? g_seqh : g_xh;
    const uint16_t* Al = asel ? g_seql : g_xl;
    const uint16_t* Bh = (wsel == 0) ? g_w0h : (wsel == 1 ? g_w1h : g_w2h);
    const uint16_t* Bl = (wsel == 0) ? g_w0l : (wsel == 1 ? g_w1l : g_w2l);

    const uint16_t* srcs[4] = {Ah + (size_t)m0 * K, Al + (size_t)m0 * K,
                               Bh + (size_t)n0 * K, Bl + (size_t)n0 * K};

    const int nC = K >> 6;

    {
#pragma unroll
        for (int i = 0; i < 16; ++i) {
            int idx  = tid + (i << 8);
            int tile = idx >> 10;
            int rem  = idx & 1023;
            int row  = rem >> 3;
            int c    = rem & 7;
            uint32_t dst = sbase + tile * (TILE_ELEM * 2) + row * (TPITCH * 2) + c * 16;
            cp_async16(dst, srcs[tile] + (size_t)row * K + c * 8);
        }
        cp_commit();
    }

    wmma::fragment<wmma::accumulator, 16, 16, 16, float> acc[2][4];
#pragma unroll
    for (int m = 0; m < 2; ++m)
#pragma unroll
        for (int n = 0; n < 4; ++n) wmma::fill_fragment(acc[m][n], 0.0f);

    const int wm = wid & 3;
    const int wn = wid >> 2;

    for (int c = 0; c < nC; ++c) {
        const int buf = c & 1;
        if (c + 1 < nC) {
            const int k0 = (c + 1) << 6;
            const uint32_t bb = sbase + ((buf ^ 1) ? BUF_ELEM * 2 : 0);
#pragma unroll
            for (int i = 0; i < 16; ++i) {
                int idx  = tid + (i << 8);
                int tile = idx >> 10;
                int rem  = idx & 1023;
                int row  = rem >> 3;
                int cc   = rem & 7;
                uint32_t dst = bb + tile * (TILE_ELEM * 2) + row * (TPITCH * 2) + cc * 16;
                cp_async16(dst, srcs[tile] + (size_t)row * K + k0 + cc * 8);
            }
            cp_commit();
            cp_wait<1>();
        } else {
            cp_wait<0>();
        }
        __syncthreads();

        const __nv_bfloat16* bufp = smem + buf * BUF_ELEM;
        const __nv_bfloat16* sAh = bufp;
        const __nv_bfloat16* sAl = bufp + TILE_ELEM;
        const __nv_bfloat16* sBh = bufp + 2 * TILE_ELEM;
        const __nv_bfloat16* sBl = bufp + 3 * TILE_ELEM;

#pragma unroll
        for (int ks = 0; ks < 4; ++ks) {
            wmma::fragment<wmma::matrix_a, 16, 16, 16, __nv_bfloat16, wmma::row_major> ah[2], al[2];
#pragma unroll
            for (int m = 0; m < 2; ++m) {
                wmma::load_matrix_sync(ah[m], sAh + (wm * 32 + m * 16) * TPITCH + ks * 16, TPITCH);
                wmma::load_matrix_sync(al[m], sAl + (wm * 32 + m * 16) * TPITCH + ks * 16, TPITCH);
            }
#pragma unroll
            for (int n = 0; n < 4; ++n) {
                wmma::fragment<wmma::matrix_b, 16, 16, 16, __nv_bfloat16, wmma::col_major> bh, bl;
                wmma::load_matrix_sync(bh, sBh + (wn * 64 + n * 16) * TPITCH + ks * 16, TPITCH);
#pragma unroll
                for (int m = 0; m < 2; ++m) {
                    wmma::mma_sync(acc[m][n], ah[m], bh, acc[m][n]);
                    wmma::mma_sync(acc[m][n], al[m], bh, acc[m][n]);
                }
                wmma::load_matrix_sync(bl, sBl + (wn * 64 + n * 16) * TPITCH + ks * 16, TPITCH);
#pragma unroll
                for (int m = 0; m < 2; ++m)
                    wmma::mma_sync(acc[m][n], ah[m], bl, acc[m][n]);
            }
        }
        __syncthreads();
    }

#pragma unroll
    for (int m = 0; m < 2; ++m)
#pragma unroll
        for (int n = 0; n < 4; ++n) {
            float* dst = g_xg_mn + (size_t)(m0 + wm * 32 + m * 16) * G3_
                                 + n0 + wn * 64 + n * 16;
            wmma::store_matrix_sync(dst, acc[m][n], G3_, wmma::mem_row_major);
        }
}

// ---------------- transpose [m][n] -> [t][gate][b], add bias ----------------
__global__ __launch_bounds__(256)
void xg_trans_kernel(const float* __restrict__ bias) {
    __shared__ float sm[64][33];
    const int t   = blockIdx.x;
    const int g0  = blockIdx.y * 32;
    const int tid = threadIdx.x;
    const int gg  = tid & 31;
    const int br  = tid >> 5;
    const float bv = bias[g0 + gg];
#pragma unroll
    for (int i = 0; i < 8; ++i) {
        int b = br + i * 8;
        sm[b][gg] = g_xg_mn[((size_t)b * T_ + t) * G3_ + g0 + gg] + bv;
    }
    __syncthreads();
    const int b  = tid & 63;
    const int gi = tid >> 6;
#pragma unroll
    for (int i = 0; i < 8; ++i) {
        int g = gi + i * 4;
        g_xg[((size_t)t * G3_ + g0 + g) * B_ + b] = sm[b][g];
    }
}

// ---------------- persistent GRU recurrence (8-CTA cluster per batch group) ----------------
// Cluster = one batch group (4 batches), CTA rank = unit group (32 units).
// h exchange: producer lanes push hnew into all 8 CTAs' hs smem via
// st.shared::cluster (double-buffered by step parity); signaling via a
// 2-deep mbarrier ring (count=8, one arrive per CTA per peer).
__global__ __launch_bounds__(RT_, 1) __cluster_dims__(GU_, 1, 1)
void gru_recur_kernel(const float* __restrict__ w_hh,
                      const float* __restrict__ b_hh,
                      int layer)
{
    extern __shared__ float smf[];
    float* ws = smf + 16;                    // [96][WPITCH]
    float* hs = ws + 3 * UC_ * WPITCH;       // [2][4][WPITCH]
    const uint32_t sbase = smem_u32(smf);
    const uint32_t mbar0 = sbase;            // 2 x u64 mbarriers at offset 0
    (void)layer;

    const int t   = threadIdx.x;
    const int u   = t >> 3;                  // unit 0..31
    const int sl  = t & 7;                   // k slice 0..7
    const uint32_t rank = cluster_rank();    // unit group 0..7
    const int bg  = blockIdx.x / GU_;
    const int b0  = bg * BC_;
    const int u0  = (int)rank * UC_;
    const int gj  = u0 + u;

    // load this CTA's 96 w_hh rows (3 gates x 32 units)
    for (int q = t; q < 96 * 64; q += RT_) {
        int row = q >> 6;
        int c4  = (q & 63) << 2;
        int g   = row >> 5;
        int uu  = row & 31;
        *(float4*)&ws[row * WPITCH + c4] =
            *(const float4*)&w_hh[((size_t)(g * H_ + u0 + uu)) * H_ + c4];
    }
    // zero both h buffers
    for (int q = t; q < 2 * BC_ * WPITCH; q += RT_) hs[q] = 0.0f;

    if (t == 0) { MBARRIER_INIT(mbar0, GU_); MBARRIER_INIT(mbar0 + 8, GU_); }
    __syncthreads();
    CLUSTER_SYNC();   // mbarriers + hs init visible cluster-wide

    const float bhr = b_hh[gj];
    const float bhz = b_hh[H_ + gj];
    const float bhn = b_hh[2 * H_ + gj];
    const float* wr = &ws[(0 * UC_ + u) * WPITCH];
    const float* wz = &ws[(1 * UC_ + u) * WPITCH];
    const float* wn = &ws[(2 * UC_ + u) * WPITCH];

    // precompute peer DSMEM addresses for this lane's publish slot (sl<4)
    const uint32_t hs_base = smem_u32(hs);
    const uint32_t myoff = ((uint32_t)((sl & 3) * WPITCH + gj)) * 4;
    uint32_t peer_hs[GU_], peer_mb[GU_];
#pragma unroll
    for (int r = 0; r < GU_; ++r) {
        asm("mapa.shared::cluster.u32 %0, %1, %2;"
            : "=r"(peer_hs[r]) : "r"(hs_base + myoff), "r"(r));
        asm("mapa.shared::cluster.u32 %0, %1, %2;"
            : "=r"(peer_mb[r]) : "r"(mbar0), "r"(r));
    }

    __nv_bfloat16* outh = (__nv_bfloat16*)g_seqh;
    __nv_bfloat16* outl = (__nv_bfloat16*)g_seql;
    const uint32_t BUFB = BC_ * WPITCH * 4;  // bytes per h buffer

    for (int step = 0; step < T_; ++step) {
        const float* hrd = hs + (step & 1) * (BC_ * WPITCH);

        // prefetch xg (precomputed, independent of exchange): lanes sl<4, batch sl
        float xr = 0.f, xz = 0.f, xn = 0.f;
        if (sl < 4) {
            const float* xgp = g_xg + (size_t)step * G3_ * B_;
            xr = __ldg(&xgp[(0 * H_ + gj) * B_ + b0 + sl]);
            xz = __ldg(&xgp[(1 * H_ + gj) * B_ + b0 + sl]);
            xn = __ldg(&xgp[(2 * H_ + gj) * B_ + b0 + sl]);
        }

        // 3 gates x 4 batches over this thread's 32-k slice (interleaved)
        float acc[3][4];
#pragma unroll
        for (int g = 0; g < 3; ++g)
#pragma unroll
            for (int b = 0; b < 4; ++b) acc[g][b] = 0.f;

#pragma unroll
        for (int c = 0; c < 8; ++c) {
            const int kb = c * 32 + sl * 4;
            float4 h4[4];
#pragma unroll
            for (int b = 0; b < 4; ++b)
                h4[b] = *(const float4*)&hrd[b * WPITCH + kb];
            {
                float4 w4 = *(const float4*)&wr[kb];
#pragma unroll
                for (int b = 0; b < 4; ++b) {
                    acc[0][b] = fmaf(w4.x, h4[b].x, acc[0][b]);
                    acc[0][b] = fmaf(w4.y, h4[b].y, acc[0][b]);
                    acc[0][b] = fmaf(w4.z, h4[b].z, acc[0][b]);
                    acc[0][b] = fmaf(w4.w, h4[b].w, acc[0][b]);
                }
            }
            {
                float4 w4 = *(const float4*)&wz[kb];
#pragma unroll
                for (int b = 0; b < 4; ++b) {
                    acc[1][b] = fmaf(w4.x, h4[b].x, acc[1][b]);
                    acc[1][b] = fmaf(w4.y, h4[b].y, acc[1][b]);
                    acc[1][b] = fmaf(w4.z, h4[b].z, acc[1][b]);
                    acc[1][b] = fmaf(w4.w, h4[b].w, acc[1][b]);
                }
            }
            {
                float4 w4 = *(const float4*)&wn[kb];
#pragma unroll
                for (int b = 0; b < 4; ++b) {
                    acc[2][b] = fmaf(w4.x, h4[b].x, acc[2][b]);
                    acc[2][b] = fmaf(w4.y, h4[b].y, acc[2][b]);
                    acc[2][b] = fmaf(w4.z, h4[b].z, acc[2][b]);
                    acc[2][b] = fmaf(w4.w, h4[b].w, acc[2][b]);
                }
            }
        }

        // reduce across 8 k-slices (3-round butterfly inside 8-lane groups)
#pragma unroll
        for (int off = 4; off >= 1; off >>= 1)
#pragma unroll
            for (int g = 0; g < 3; ++g)
#pragma unroll
                for (int b = 0; b < 4; ++b)
                    acc[g][b] += __shfl_xor_sync(0xffffffffu, acc[g][b], off);

        float hnew = 0.f;
        if (sl < 4) {
            float r = 1.0f / (1.0f + __expf(-(xr + acc[0][sl] + bhr)));
            float z = 1.0f / (1.0f + __expf(-(xz + acc[1][sl] + bhz)));
            float n = tanhf(xn + r * (acc[2][sl] + bhn));
            float hold = hrd[sl * WPITCH + gj];
            hnew = (1.0f - z) * n + z * hold;
        }

        if (step + 1 < T_) {
            // publish hnew into buffer (step+1)&1 of ALL cluster CTAs
            if (sl < 4) {
                const uint32_t boff = ((step + 1) & 1) * BUFB;
#pragma unroll
                for (int r = 0; r < GU_; ++r)
                    asm volatile("st.shared::cluster.f32 [%0], %1;"
                                 :: "r"(peer_hs[r] + boff), "f"(hnew) : "memory");
            }
            __syncthreads();
            if (t == 0) {
                asm volatile("fence.acq_rel.cluster;" ::: "memory");
                const uint32_t mo = (step & 1) ? 8u : 0u;
#pragma unroll
                for (int r = 0; r < GU_; ++r)
                    asm volatile("mbarrier.arrive.shared::cluster.b64 _, [%0];"
                                 :: "r"(peer_mb[r] + mo) : "memory");
            }
            // overlap: seq outputs while peers arrive
            if (sl < 4) {
                __nv_bfloat16 hh = __float2bfloat16(hnew);
                __nv_bfloat16 hl = __float2bfloat16(hnew - __bfloat162float(hh));
                size_t o = ((size_t)(b0 + sl) * T_ + step) * H_ + gj;
                outh[o] = hh;
                outl[o] = hl;
            }
            // wait for all 8 CTAs' step-s publishes
            MBARRIER_WAIT_CLUSTER(mbar0 + ((step & 1) ? 8u : 0u), (uint32_t)((step >> 1) & 1));
        } else {
            if (sl < 4) {
                __nv_bfloat16 hh = __float2bfloat16(hnew);
                __nv_bfloat16 hl = __float2bfloat16(hnew - __bfloat162float(hh));
                size_t o = ((size_t)(b0 + sl) * T_ + step) * H_ + gj;
                outh[o] = hh;
                outl[o] = hl;
                __stcg(&g_h[0][(b0 + sl) * H_ + gj], hnew);   // for the head
            }
        }
    }
    CLUSTER_SYNC();   // no CTA exits while peers may still store into its smem
}

// ---------------- MLP head ----------------
__global__ void head_kernel(const float* __restrict__ fc1_w,
                            const float* __restrict__ fc1_b,
                            const float* __restrict__ fco_w,
                            const float* __restrict__ fco_b,
                            float* __restrict__ outp)
{
    const int b = blockIdx.x;
    const int f = threadIdx.x;
    const float* last = &g_h[0][b * H_];
    float acc = fc1_b[f];
#pragma unroll 4
    for (int k = 0; k < H_; k += 4) {
        float4 l4 = *(const float4*)&last[k];
        float4 w4 = *(const float4*)&fc1_w[(size_t)f * H_ + k];
        acc = fmaf(l4.x, w4.x, acc); acc = fmaf(l4.y, w4.y, acc);
        acc = fmaf(l4.z, w4.z, acc); acc = fmaf(l4.w, w4.w, acc);
    }
    float zz = fmaxf(acc, 0.0f) * fco_w[f];
#pragma unroll
    for (int o = 16; o > 0; o >>= 1)
        zz += __shfl_down_sync(0xffffffffu, zz, o);
    __shared__ float red4[4];
    if ((f & 31) == 0) red4[f >> 5] = zz;
    __syncthreads();
    if (f == 0) outp[b] = red4[0] + red4[1] + red4[2] + red4[3] + fco_b[0];
}

// ---------------- launch ----------------
extern "C" void kernel_launch(void* const* d_in, const int* in_sizes, int n_in,
                              void* d_out, int out_size) {
    (void)in_sizes; (void)n_in; (void)out_size;
    const float* x      = (const float*)d_in[0];
    const float* wih[3] = {(const float*)d_in[1], (const float*)d_in[5], (const float*)d_in[9]};
    const float* whh[3] = {(const float*)d_in[2], (const float*)d_in[6], (const float*)d_in[10]};
    const float* bih[3] = {(const float*)d_in[3], (const float*)d_in[7], (const float*)d_in[11]};
    const float* bhh[3] = {(const float*)d_in[4], (const float*)d_in[8], (const float*)d_in[12]};
    const float* fc1_w  = (const float*)d_in[13];
    const float* fc1_b  = (const float*)d_in[14];
    const float* fco_w  = (const float*)d_in[15];
    const float* fco_b  = (const float*)d_in[16];
    float* outp = (float*)d_out;

    cudaFuncSetAttribute(proj_wmma_kernel,
                         cudaFuncAttributeMaxDynamicSharedMemorySize, PSMEM);
    cudaFuncSetAttribute(gru_recur_kernel,
                         cudaFuncAttributeMaxDynamicSharedMemorySize, RSMEM);

    init_kernel<<<128, 256>>>();                                    // 1
    split_x_kernel<<<2048, 256>>>(x);                               // 2
    split_w_kernel<<<dim3(256, 3), 256>>>(wih[0], wih[1], wih[2]);  // 3

    dim3 pgrid(M_ / 128, G3_ / 128);
    dim3 tgrid(T_, G3_ / 32);
    const int Ks[3]   = {K0_, H_, H_};
    const int asel[3] = {0, 1, 1};

    for (int l = 0; l < 3; ++l) {
        proj_wmma_kernel<<<pgrid, 256, PSMEM>>>(Ks[l], asel[l], l);   // 4
        xg_trans_kernel<<<tgrid, 256>>>(bih[l]);                      // 5
        gru_recur_kernel<<<GB_ * GU_, RT_, RSMEM>>>(whh[l], bhh[l], l); // 6
    }
    head_kernel<<<B_, 128>>>(fc1_w, fc1_b, fco_w, fco_b, outp);
}